// round 9
// baseline (speedup 1.0000x reference)
#include <cuda_runtime.h>
#include <math.h>

#define NN 50000
#define FF 64
#define EE 1600000
#define HH 16
#define AA 8
#define NFIELD 8   /* 1 + RECEPTIVE_FIELD */

// ---------------- static device scratch (no allocations allowed) ----------------
__device__ __align__(16) int   g_deg[NN];
__device__ __align__(16) int   g_cursor[NN];
__device__ __align__(16) int   g_off[NN + 1];
__device__ __align__(16) int   g_csr[EE];
__device__ __align__(16) float g_za[NN * HH];        // ping
__device__ __align__(16) float g_zb[NN * HH];        // pong
__device__ __align__(16) float g_r[NFIELD * NN * HH];// relu2 hidden per field
__device__ __align__(16) float g_W31[HH * HH];       // w3 @ w1   [16,16]
__device__ __align__(16) float g_b31[HH];            // b3 @ w1   [16]
__device__ __align__(16) float g_T[NFIELD * FF * AA];// fc1_w @ fc2_w  [512,8]
__device__ __align__(16) float g_G[NFIELD * HH * AA];// w3 @ fc1_blk_i @ fc2_w
__device__ __align__(16) float g_bias[AA];           // folded logit bias
__device__ int g_odd_nonzero;                        // dtype detection scratch

// ---------------- tiny precompute of folded weight matrices ----------------
__global__ void k_pre(const float* __restrict__ w1, const float* __restrict__ b1,
                      const float* __restrict__ w3, const float* __restrict__ b3,
                      const float* __restrict__ fc1w, const float* __restrict__ fc1b,
                      const float* __restrict__ fc2w, const float* __restrict__ fc2b) {
    int t = threadIdx.x;  // 512 threads, 1 block
    if (t < HH * HH) {
        int k = t >> 4, j = t & 15;
        float s = 0.f;
        for (int f = 0; f < FF; f++) s += w3[k * FF + f] * w1[f * HH + j];
        g_W31[t] = s;
    }
    if (t < HH) {
        float s = 0.f;
        for (int f = 0; f < FF; f++) s += b3[f] * w1[f * HH + t];
        g_b31[t] = s;
    }
    // T[t][a] = sum_k fc1w[t][k] * fc2w[k][a]   (t in [0,512))
    {
        float s[AA];
        #pragma unroll
        for (int a = 0; a < AA; a++) s[a] = 0.f;
        for (int k = 0; k < FF; k++) {
            float v = fc1w[t * FF + k];
            #pragma unroll
            for (int a = 0; a < AA; a++) s[a] += v * fc2w[k * AA + a];
        }
        #pragma unroll
        for (int a = 0; a < AA; a++) g_T[t * AA + a] = s[a];
    }
    __syncthreads();
    // G[i][j][a] = sum_f w3[j][f] * T[i*64+f][a]
    if (t < NFIELD * HH) {
        int i = t >> 4, j = t & 15;
        float s[AA];
        #pragma unroll
        for (int a = 0; a < AA; a++) s[a] = 0.f;
        for (int f = 0; f < FF; f++) {
            float v = w3[j * FF + f];
            #pragma unroll
            for (int a = 0; a < AA; a++) s[a] += v * g_T[(i * FF + f) * AA + a];
        }
        #pragma unroll
        for (int a = 0; a < AA; a++) g_G[t * AA + a] = s[a];
    }
    // bias[a] = fc2b[a] + fc1b@fc2w + sum_i (b3 @ fc1_blk_i) @ fc2w
    if (t < AA) {
        float s = fc2b[t];
        for (int k = 0; k < FF; k++) s += fc1b[k] * fc2w[k * AA + t];
        for (int q = 0; q < NFIELD * FF; q++) s += b3[q & (FF - 1)] * g_T[q * AA + t];
        g_bias[t] = s;
    }
}

// ---------------- edge dtype detection + CSR build ----------------
// edge_index is logically (2, E) of node ids in [0, N). It may be stored as
// int32 (JAX default, x64 disabled) or int64. We read it as int32 words.
// For int64 little-endian, the word at odd offset 2*i+1 within the first
// 2*EE words (the guaranteed-size span) is the high half of element i and is
// always 0; for int32 it's a node id (~never 0 across 4096 samples).
__global__ void k_zero() {
    int i = blockIdx.x * 256 + threadIdx.x;
    if (i < NN) { g_deg[i] = 0; g_cursor[i] = 0; }
    if (i == 0) g_odd_nonzero = 0;
}

__global__ void k_detect(const int* __restrict__ w) {
    int t = blockIdx.x * 256 + threadIdx.x;   // 4096 threads
    long long i = (long long)t * (EE / 4096); // i in [0, EE)
    if (w[2 * i + 1] != 0) atomicOr(&g_odd_nonzero, 1);
}

__device__ __forceinline__ void load_edge(const int* __restrict__ w, int e, int is64,
                                          int& s, int& d) {
    if (is64) {
        s = w[2 * e];                 // low word of row-0 element e
        d = w[2 * (long long)EE + 2 * e];
    } else {
        s = w[e];
        d = w[EE + e];
    }
}

__global__ void k_hist(const int* __restrict__ w) {
    int e = blockIdx.x * 256 + threadIdx.x;
    if (e < EE) {
        int is64 = (g_odd_nonzero == 0);
        int s, d;
        load_edge(w, e, is64, s, d);
        if ((unsigned)d < (unsigned)NN) atomicAdd(&g_deg[d], 1);
    }
}

__global__ void k_scan() {
    __shared__ int ssum[1024];
    int tid = threadIdx.x;
    const int CH = (NN + 1023) / 1024;  // 49
    int base = tid * CH;
    int s = 0;
    for (int i = 0; i < CH; i++) {
        int idx = base + i;
        if (idx < NN) s += g_deg[idx];
    }
    ssum[tid] = s;
    __syncthreads();
    for (int st = 1; st < 1024; st <<= 1) {
        int v = (tid >= st) ? ssum[tid - st] : 0;
        __syncthreads();
        ssum[tid] += v;
        __syncthreads();
    }
    int run = (tid == 0) ? 0 : ssum[tid - 1];
    for (int i = 0; i < CH; i++) {
        int idx = base + i;
        if (idx < NN) { g_off[idx] = run; run += g_deg[idx]; }
    }
    if (tid == 0) g_off[NN] = EE;
}

__global__ void k_fill(const int* __restrict__ w) {
    int e = blockIdx.x * 256 + threadIdx.x;
    if (e < EE) {
        int is64 = (g_odd_nonzero == 0);
        int s, d;
        load_edge(w, e, is64, s, d);
        if ((unsigned)d < (unsigned)NN && (unsigned)s < (unsigned)NN) {
            int p = atomicAdd(&g_cursor[d], 1);
            int idx = g_off[d] + p;
            if ((unsigned)idx < (unsigned)EE) g_csr[idx] = s;
        }
    }
}

// ---------------- front: x -> z0 = (mlp(x)) @ w1, and relu2_0 ----------------
__global__ void __launch_bounds__(256) k_front(const float* __restrict__ x,
                                               const float* __restrict__ w1, const float* __restrict__ b1,
                                               const float* __restrict__ w2, const float* __restrict__ b2) {
    __shared__ float s_w1[FF * HH];
    __shared__ float s_w2[HH * HH];
    __shared__ float s_W31[HH * HH];
    __shared__ float s_b1[HH], s_b2[HH], s_b31[HH];
    __shared__ float s_x[8][FF];
    int tid = threadIdx.x;
    for (int i = tid; i < FF * HH; i += 256) s_w1[i] = w1[i];
    if (tid < HH * HH) { s_w2[tid] = w2[tid]; s_W31[tid] = g_W31[tid]; }
    if (tid < HH) { s_b1[tid] = b1[tid]; s_b2[tid] = b2[tid]; s_b31[tid] = g_b31[tid]; }
    __syncthreads();
    int warp = tid >> 5, lane = tid & 31;
    int n = blockIdx.x * 8 + warp;   // grid = NN/8 exactly, no stragglers

    s_x[warp][lane]      = x[n * FF + lane];
    s_x[warp][lane + 32] = x[n * FF + lane + 32];
    __syncwarp();

    int j = lane & 15;
    // hidden of mlp(x)
    float h1 = s_b1[j];
    #pragma unroll 16
    for (int f = 0; f < FF; f++) h1 += s_x[warp][f] * s_w1[f * HH + j];
    h1 = fmaxf(h1, 0.f);
    float h2 = s_b2[j];
    #pragma unroll
    for (int k = 0; k < HH; k++) h2 += __shfl_sync(0xffffffffu, h1, k) * s_w2[k * HH + j];
    h2 = fmaxf(h2, 0.f);
    // z0 = h2 @ (w3@w1) + (b3@w1)
    float z = s_b31[j];
    #pragma unroll
    for (int k = 0; k < HH; k++) z += __shfl_sync(0xffffffffu, h2, k) * s_W31[k * HH + j];
    if (lane < HH) g_za[n * HH + j] = z;
    // relu2_0 = hidden of mlp applied to m  (z already = m@w1)
    float h1b = fmaxf(z + s_b1[j], 0.f);
    float h2b = s_b2[j];
    #pragma unroll
    for (int k = 0; k < HH; k++) h2b += __shfl_sync(0xffffffffu, h1b, k) * s_w2[k * HH + j];
    h2b = fmaxf(h2b, 0.f);
    if (lane < HH) g_r[n * HH + j] = h2b;
}

// ---------------- agg: z_out = mean over in-edges of z_in, fused relu2 ----------------
__global__ void __launch_bounds__(256) k_agg(int pass,
                                             const float* __restrict__ b1,
                                             const float* __restrict__ w2,
                                             const float* __restrict__ b2) {
    __shared__ float s_w2[HH * HH];
    __shared__ float s_b1[HH], s_b2[HH];
    int tid = threadIdx.x;
    if (tid < HH * HH) s_w2[tid] = w2[tid];
    if (tid < HH) { s_b1[tid] = b1[tid]; s_b2[tid] = b2[tid]; }
    __syncthreads();
    int warp = tid >> 5, lane = tid & 31;
    int n = blockIdx.x * 8 + warp;   // grid = NN/8 exactly

    const float* zin = (pass & 1) ? g_za : g_zb;
    float*       zout = (pass & 1) ? g_zb : g_za;
    float*       rout = g_r + (size_t)pass * (size_t)NN * HH;

    int beg = g_off[n];
    int end = g_off[n + 1];
    int deg = end - beg;
    int f  = lane & 15;   // feature
    int eo = lane >> 4;   // which of 2 edges per iteration

    float acc = 0.f;
    int npair = deg >> 1;
    int it = 0;
    for (; it + 4 <= npair; it += 4) {
        int s0 = g_csr[beg + 2 * it + 0 + eo];
        int s1 = g_csr[beg + 2 * it + 2 + eo];
        int s2 = g_csr[beg + 2 * it + 4 + eo];
        int s3 = g_csr[beg + 2 * it + 6 + eo];
        float v0 = zin[s0 * HH + f];
        float v1 = zin[s1 * HH + f];
        float v2 = zin[s2 * HH + f];
        float v3 = zin[s3 * HH + f];
        acc += (v0 + v1) + (v2 + v3);
    }
    for (; it < npair; it++) {
        int s = g_csr[beg + 2 * it + eo];
        acc += zin[s * HH + f];
    }
    if ((deg & 1) && eo == 0) acc += zin[g_csr[beg + deg - 1] * HH + f];

    acc += __shfl_xor_sync(0xffffffffu, acc, 16);
    float z = (deg > 0) ? acc / (float)deg : 0.f;
    if (lane < HH) zout[n * HH + f] = z;

    // fused relu2 epilogue
    float h1 = fmaxf(z + s_b1[f], 0.f);
    float h2 = s_b2[f];
    #pragma unroll
    for (int k = 0; k < HH; k++) h2 += __shfl_sync(0xffffffffu, h1, k) * s_w2[k * HH + f];
    h2 = fmaxf(h2, 0.f);
    if (lane < HH) rout[n * HH + f] = h2;
}

// ---------------- final head: logits = bias + sum_i relu2_i @ G_i ; softmax ----------------
__global__ void __launch_bounds__(256) k_final(float* __restrict__ out) {
    __shared__ float sG[NFIELD * HH * AA];  // 1024 floats = 4 KB
    __shared__ float sB[AA];
    int tid = threadIdx.x;
    for (int i = tid; i < NFIELD * HH * AA; i += 256) sG[i] = g_G[i];
    if (tid < AA) sB[tid] = g_bias[tid];
    __syncthreads();
    int n = blockIdx.x * 256 + tid;
    if (n >= NN) return;

    float acc[AA];
    #pragma unroll
    for (int a = 0; a < AA; a++) acc[a] = sB[a];

    #pragma unroll
    for (int i = 0; i < NFIELD; i++) {
        const float* rp = g_r + (size_t)i * (size_t)NN * HH + (size_t)n * HH;
        const float* Gp = sG + i * HH * AA;
        #pragma unroll
        for (int jj = 0; jj < HH; jj++) {
            float r = rp[jj];
            #pragma unroll
            for (int a = 0; a < AA; a++) acc[a] += r * Gp[jj * AA + a];
        }
    }

    float mx = acc[0];
    #pragma unroll
    for (int a = 1; a < AA; a++) mx = fmaxf(mx, acc[a]);
    float sum = 0.f;
    #pragma unroll
    for (int a = 0; a < AA; a++) { acc[a] = __expf(acc[a] - mx); sum += acc[a]; }
    float inv = 1.f / sum;
    #pragma unroll
    for (int a = 0; a < AA; a++) out[(size_t)n * AA + a] = acc[a] * inv;
}

// ---------------- launch ----------------
extern "C" void kernel_launch(void* const* d_in, const int* in_sizes, int n_in,
                              void* d_out, int out_size) {
    const float* x    = (const float*)d_in[0];
    const int*   ei   = (const int*)d_in[1];   // int32 words; dtype auto-detected on device
    const float* w1   = (const float*)d_in[2];
    const float* b1   = (const float*)d_in[3];
    const float* w2   = (const float*)d_in[4];
    const float* b2   = (const float*)d_in[5];
    const float* w3   = (const float*)d_in[6];
    const float* b3   = (const float*)d_in[7];
    const float* fc1w = (const float*)d_in[8];
    const float* fc1b = (const float*)d_in[9];
    const float* fc2w = (const float*)d_in[10];
    const float* fc2b = (const float*)d_in[11];
    float* out = (float*)d_out;

    k_pre<<<1, 512>>>(w1, b1, w3, b3, fc1w, fc1b, fc2w, fc2b);
    k_zero<<<(NN + 255) / 256, 256>>>();
    k_detect<<<16, 256>>>(ei);
    k_hist<<<(EE + 255) / 256, 256>>>(ei);
    k_scan<<<1, 1024>>>();
    k_fill<<<(EE + 255) / 256, 256>>>(ei);
    k_front<<<NN / 8, 256>>>(x, w1, b1, w2, b2);
    for (int p = 1; p <= 7; p++) {
        k_agg<<<NN / 8, 256>>>(p, b1, w2, b2);
    }
    k_final<<<(NN + 255) / 256, 256>>>(out);
}